// round 5
// baseline (speedup 1.0000x reference)
#include <cuda_runtime.h>
#include <math.h>

#define Bsz 64
#define Ssz 512
#define Hsz 400
#define Dsz 400
#define Vsz 32000
#define Lsz 16
#define NPART 4          // GEMM K split
#define KC   100         // K per part
#define JT   24          // j-tile per block
#define HC   8           // h chunks in fused kernel (50 h each)
#define HCW  50          // h per chunk

// ---------------- scratch (device globals; no allocation) ----------------
__device__ float g_Gpart[NPART][Bsz][2400];  // [part][b][0:1200 gi | 1200:2400 gh]
__device__ float g_hA[Bsz * Hsz];
__device__ float g_hB[Bsz * Hsz];
__device__ float g_x[Bsz * Dsz];
__device__ float g_encT[Bsz][Hsz][Ssz];      // transposed encoder outputs (52 MB)
__device__ float g_scpart[HC][Bsz][Ssz];     // partial scores per h-chunk
__device__ int   g_cnt[Bsz];                 // arrival counters (zero-init; tail resets)

// ---------------- f32x2 packed-FMA helpers ----------------
__device__ __forceinline__ unsigned long long pk2(float x, float y) {
    unsigned long long r;
    asm("mov.b64 %0, {%1, %2};" : "=l"(r) : "f"(x), "f"(y));
    return r;
}
__device__ __forceinline__ void ffma2(unsigned long long& d,
                                      unsigned long long a, unsigned long long b) {
    asm("fma.rn.f32x2 %0, %1, %2, %0;" : "+l"(d) : "l"(a), "l"(b));
}
__device__ __forceinline__ float2 up2(unsigned long long v) {
    float2 f;
    asm("mov.b64 {%0, %1}, %2;" : "=f"(f.x), "=f"(f.y) : "l"(v));
    return f;
}

// ---------------- zero output with evict-first stores ----------------
__global__ __launch_bounds__(256) void zero_kernel(float* __restrict__ out, int n4, int n) {
    int idx = blockIdx.x * 256 + threadIdx.x;
    int stride = gridDim.x * 256;
    for (int i = idx; i < n4; i += stride) {
        float4* p = (float4*)out + i;
        asm volatile("st.global.cs.v4.f32 [%0], {%1, %2, %3, %4};"
                     :: "l"(p), "f"(0.f), "f"(0.f), "f"(0.f), "f"(0.f) : "memory");
    }
    for (int i = n4 * 4 + idx; i < n; i += stride) {
        asm volatile("st.global.cs.f32 [%0], %1;" :: "l"(out + i), "f"(0.f) : "memory");
    }
}

// ---------------- init ----------------
__global__ void init_kernel(const float* __restrict__ eh,
                            const float* __restrict__ slot_emb,
                            const int* __restrict__ slot_p) {
    int idx = blockIdx.x * blockDim.x + threadIdx.x;
    if (idx < Bsz * Hsz) {
        g_hA[idx] = eh[idx];
        int j = idx % Dsz;
        g_x[idx] = slot_emb[slot_p[0] * Dsz + j];
    }
}

// ---------------- transpose enc[b][s][h] -> encT[b][h][s] (tiled smem) ----------------
__global__ __launch_bounds__(256) void transpose_kernel(const float* __restrict__ enc) {
    __shared__ float tile[32][33];
    int b  = blockIdx.z;
    int s0 = blockIdx.x * 32;
    int h0 = blockIdx.y * 32;
    int tx = threadIdx.x, ty = threadIdx.y;   // 32 x 8

    #pragma unroll
    for (int i = 0; i < 32; i += 8) {
        int s = s0 + ty + i, h = h0 + tx;
        if (h < Hsz)
            tile[ty + i][tx] = enc[((size_t)b * Ssz + s) * Hsz + h];
    }
    __syncthreads();
    #pragma unroll
    for (int i = 0; i < 32; i += 8) {
        int h = h0 + ty + i, s = s0 + tx;
        if (h < Hsz)
            g_encT[b][h][s] = tile[tx][ty + i];
    }
}

// ---------------- K1: GEMM partials (unchanged — proven) ----------------
__global__ __launch_bounds__(96) void gemm_kernel(const float* __restrict__ Wih,
                                                  const float* __restrict__ Whh,
                                                  int t) {
    __shared__ float As[KC][68];
    __shared__ float Ws[KC][28];

    int bx = blockIdx.x;
    int mat = bx / 200;
    int rem = bx % 200;
    int jt  = rem / NPART;
    int ks  = rem % NPART;
    int jbase = jt * JT;
    int kbase = ks * KC;

    const float* hin = (t & 1) ? g_hB : g_hA;
    const float* A = mat ? hin : g_x;
    const float* W = mat ? Whh : Wih;

    int tid = threadIdx.x;

    for (int i = tid; i < 64 * (KC / 4); i += 96) {
        int q = i / 64, b = i % 64;
        float4 v = *(const float4*)&A[b * 400 + kbase + 4 * q];
        As[4 * q + 0][b] = v.x;
        As[4 * q + 1][b] = v.y;
        As[4 * q + 2][b] = v.z;
        As[4 * q + 3][b] = v.w;
    }
    for (int i = tid; i < JT * (KC / 4); i += 96) {
        int q = i / JT, j = i % JT;
        float4 v = *(const float4*)&W[(jbase + j) * 400 + kbase + 4 * q];
        Ws[4 * q + 0][j] = v.x;
        Ws[4 * q + 1][j] = v.y;
        Ws[4 * q + 2][j] = v.z;
        Ws[4 * q + 3][j] = v.w;
    }
    __syncthreads();

    int tj = tid / 16;
    int tb = tid % 16;
    int b0 = 4 * tb;
    int j0 = 4 * tj;

    unsigned long long acc[4][2];
    #pragma unroll
    for (int jj = 0; jj < 4; jj++) { acc[jj][0] = 0ULL; acc[jj][1] = 0ULL; }

    #pragma unroll 4
    for (int k = 0; k < KC; k++) {
        float4 av = *(const float4*)&As[k][b0];
        float4 wv = *(const float4*)&Ws[k][j0];
        unsigned long long a01 = pk2(av.x, av.y);
        unsigned long long a23 = pk2(av.z, av.w);
        unsigned long long w0 = pk2(wv.x, wv.x);
        unsigned long long w1 = pk2(wv.y, wv.y);
        unsigned long long w2 = pk2(wv.z, wv.z);
        unsigned long long w3 = pk2(wv.w, wv.w);
        ffma2(acc[0][0], a01, w0); ffma2(acc[0][1], a23, w0);
        ffma2(acc[1][0], a01, w1); ffma2(acc[1][1], a23, w1);
        ffma2(acc[2][0], a01, w2); ffma2(acc[2][1], a23, w2);
        ffma2(acc[3][0], a01, w3); ffma2(acc[3][1], a23, w3);
    }

    float val[4][4];
    #pragma unroll
    for (int jj = 0; jj < 4; jj++) {
        float2 lo = up2(acc[jj][0]);
        float2 hi = up2(acc[jj][1]);
        val[jj][0] = lo.x; val[jj][1] = lo.y; val[jj][2] = hi.x; val[jj][3] = hi.y;
    }
    int obase = mat * 1200 + jbase + j0;
    #pragma unroll
    for (int bb = 0; bb < 4; bb++) {
        float4 o = make_float4(val[0][bb], val[1][bb], val[2][bb], val[3][bb]);
        *(float4*)&g_Gpart[ks][b0 + bb][obase] = o;
    }
}

// ---------------- K2: fused gates(h-chunk) + broadcast-MAC scores + tail ----------
// grid = 512 (64 b x 8 h-chunks of 50), 128 threads.
__global__ __launch_bounds__(128) void fused_kernel(const int* __restrict__ lens,
                                                    const int* __restrict__ uttrs,
                                                    const int* __restrict__ targets,
                                                    const int* __restrict__ use_tf_p,
                                                    const float* __restrict__ embedding,
                                                    const float* __restrict__ bih,
                                                    const float* __restrict__ bhh,
                                                    float* __restrict__ out,
                                                    int t, int write_preds) {
    __shared__ float sh[HCW];
    __shared__ float redv[128];
    __shared__ int   redi[128];
    __shared__ int   sh_last;
    __shared__ int   sh_nxt;

    int bx = blockIdx.x;
    int b  = bx >> 3;
    int hc = bx & 7;
    int tid = threadIdx.x;

    const float* hin  = (t & 1) ? g_hB : g_hA;
    float*       hout = (t & 1) ? g_hA : g_hB;

    // ---- gates: this block owns h in [hc*50, hc*50+50) — elementwise, no redundancy ----
    if (tid < HCW) {
        int j = hc * HCW + tid;
        float ir = bih[j], iz = bih[400 + j], in_ = bih[800 + j];
        float hr = bhh[j], hz = bhh[400 + j], hn = bhh[800 + j];
        #pragma unroll
        for (int p = 0; p < NPART; p++) {
            const float* P = &g_Gpart[p][b][0];
            ir += P[j];         iz += P[400 + j];  in_ += P[800 + j];
            hr += P[1200 + j];  hz += P[1600 + j]; hn += P[2000 + j];
        }
        float r = 1.f / (1.f + expf(-(ir + hr)));
        float z = 1.f / (1.f + expf(-(iz + hz)));
        float n = tanhf(in_ + r * hn);
        float hnew = (1.f - z) * n + z * hin[b * 400 + j];
        sh[tid] = hnew;
        hout[b * 400 + j] = hnew;          // each h written exactly once across chunks
    }
    __syncthreads();

    // ---- partial scores: thread owns 4 s, broadcast-MAC over 50 h, no reductions ----
    int len = lens[b];
    int s0 = 4 * tid;
    if (s0 < len) {
        const float4* ep = (const float4*)&g_encT[b][hc * HCW][0] + tid;  // stride 128/h
        float4 acc = make_float4(0.f, 0.f, 0.f, 0.f);
        #pragma unroll 10
        for (int h = 0; h < HCW; h++) {
            float hv = sh[h];
            float4 e = ep[(size_t)h * 128];
            acc.x += e.x * hv; acc.y += e.y * hv;
            acc.z += e.z * hv; acc.w += e.w * hv;
        }
        *(float4*)&g_scpart[hc][b][s0] = acc;
    }

    // ---- last-block-per-b becomes the softmax tail ----
    __threadfence();
    __syncthreads();
    if (tid == 0) {
        int old = atomicAdd(&g_cnt[b], 1);
        sh_last = (old == HC - 1);
    }
    __syncthreads();
    if (!sh_last) return;
    __threadfence();                    // acquire peers' partial writes
    if (tid == 0) g_cnt[b] = 0;

    // combine partials: thread owns s = tid + 128*q (q ascending => s ascending)
    float v[4];
    #pragma unroll
    for (int q = 0; q < 4; q++) {
        int s = tid + 128 * q;
        if (s < len) {
            float sum = 0.f;
            #pragma unroll
            for (int p = 0; p < HC; p++) sum += g_scpart[p][b][s];
            v[q] = sum;
        } else {
            v[q] = -INFINITY;
        }
    }

    // local first-index max (ascending s within thread), then block reduce with
    // min-index tie-break (jnp.argmax semantics)
    float mv = v[0]; int mi = tid;
    #pragma unroll
    for (int q = 1; q < 4; q++) {
        if (v[q] > mv) { mv = v[q]; mi = tid + 128 * q; }
    }
    redv[tid] = mv;
    redi[tid] = mi;
    __syncthreads();
    for (int st = 64; st > 0; st >>= 1) {
        if (tid < st) {
            float w2 = redv[tid + st];
            int   i2 = redi[tid + st];
            if (w2 > redv[tid] || (w2 == redv[tid] && i2 < redi[tid])) {
                redv[tid] = w2;
                redi[tid] = i2;
            }
        }
        __syncthreads();
    }
    float m = redv[0];
    int amax = redi[0];
    __syncthreads();

    float e[4], lsum = 0.f;
    #pragma unroll
    for (int q = 0; q < 4; q++) {
        e[q] = expf(v[q] - m);          // exp(-inf - m) = 0 for masked
        lsum += e[q];
    }
    redv[tid] = lsum;
    __syncthreads();
    for (int st = 64; st > 0; st >>= 1) {
        if (tid < st) redv[tid] += redv[tid + st];
        __syncthreads();
    }
    float inv = 1.f / redv[0];

    float* orow = out + (size_t)b * Lsz * Vsz + (size_t)t * Vsz;
    #pragma unroll
    for (int q = 0; q < 4; q++) {
        int s = tid + 128 * q;
        if (s < len)
            atomicAdd(&orow[uttrs[b * Ssz + s]], e[q] * inv);
    }

    if (tid == 0) {
        int pred = uttrs[b * Ssz + amax];
        if (write_preds)
            out[(size_t)Bsz * Lsz * Vsz + (size_t)t * Bsz + b] = (float)pred;
        sh_nxt = use_tf_p[0] ? targets[b * Lsz + t] : pred;
    }
    __syncthreads();

    if (tid < 100) {
        ((float4*)(g_x + b * Dsz))[tid] =
            ((const float4*)(embedding + (size_t)sh_nxt * Dsz))[tid];
    }
}

// ---------------- launch ----------------
extern "C" void kernel_launch(void* const* d_in, const int* in_sizes, int n_in,
                              void* d_out, int out_size) {
    const float* eh       = (const float*)d_in[0];
    const float* enc      = (const float*)d_in[1];
    const int*   lens     = (const int*)d_in[2];
    const int*   uttrs    = (const int*)d_in[3];
    const int*   targets  = (const int*)d_in[4];
    const int*   slot     = (const int*)d_in[5];
    const int*   use_tf   = (const int*)d_in[6];
    const float* emb      = (const float*)d_in[7];
    const float* slot_emb = (const float*)d_in[8];
    const float* Wih      = (const float*)d_in[9];
    const float* Whh      = (const float*)d_in[10];
    const float* bih      = (const float*)d_in[11];
    const float* bhh      = (const float*)d_in[12];
    float* out = (float*)d_out;

    zero_kernel<<<1184, 256>>>(out, out_size / 4, out_size);
    init_kernel<<<50, 512>>>(eh, slot_emb, slot);
    {
        dim3 tgrid(Ssz / 32, (Hsz + 31) / 32, Bsz);
        dim3 tblk(32, 8);
        transpose_kernel<<<tgrid, tblk>>>(enc);
    }

    int write_preds = out_size > Bsz * Lsz * Vsz;
    for (int t = 0; t < Lsz; t++) {
        gemm_kernel<<<400, 96>>>(Wih, Whh, t);
        fused_kernel<<<512, 128>>>(lens, uttrs, targets, use_tf, emb,
                                   bih, bhh, out, t, write_preds);
    }
}